// round 4
// baseline (speedup 1.0000x reference)
#include <cuda_runtime.h>
#include <math.h>

// Problem dims (fixed by dataset)
#define MAXN 50000
#define MAXE 850000   // 800000 edges + 50000 self loops
#define IN_DIM 256
#define H1DIM 128     // 8 heads * 16
#define HEADS1 8
#define C1 16
#define H2DIM 64
#define NEG_SLOPE 0.2f

// ---------------- scratch (static device globals; no allocation) -------------
__device__ float g_h1[MAXN * H1DIM];
__device__ float g_s1src[MAXN * HEADS1];
__device__ float g_s1dst[MAXN * HEADS1];
__device__ int   g_deg[MAXN];
__device__ int   g_rowptr[MAXN + 1];
__device__ int   g_cursor[MAXN];
__device__ int   g_esrc[MAXE];
__device__ int   g_edst[MAXE];
__device__ float g_elog[MAXE * HEADS1];
__device__ float g_out1[MAXN * H1DIM];
__device__ float g_h2[MAXN * H2DIM];
__device__ float g_s2src[MAXN];
__device__ float g_s2dst[MAXN];
__device__ float g_ew2[MAXE];
__device__ int   g_is64;   // 1 if edge_index buffer is int64, 0 if int32

// ---------------- edge dtype detection --------------------------------------
// For int64 nonnegative data, odd 32-bit words are zero high-words.
// For int32 data, 64 random values in [0,50000) being all zero is impossible.
__global__ void detect_kernel(const int* __restrict__ ei32) {
    if (threadIdx.x == 0 && blockIdx.x == 0) {
        int all_zero = 1;
        for (int i = 0; i < 64; i++)
            if (ei32[2 * i + 1] != 0) { all_zero = 0; break; }
        g_is64 = all_zero;
    }
}

__device__ __forceinline__ int edge_at(const void* ei, size_t idx) {
    if (g_is64) return (int)((const long long*)ei)[idx];
    return ((const int*)ei)[idx];
}

// ---------------- GEMM: C[M,N] = A[M,K] @ B[K,N] -----------------------------
// WHICH==0: A = arg (x), C = g_h1.   WHICH==1: A = g_out1, C = g_h2.
// BM=64, BK=16. 256 threads; warp owns 8 rows, lane owns VN cols.
template <int BN, int VN, int WHICH>
__global__ __launch_bounds__(256)
void gemm_kernel(const float* __restrict__ Aarg, const float* __restrict__ B,
                 int M, int K, int N) {
    const float* __restrict__ A = (WHICH == 0) ? Aarg : (const float*)g_out1;
    float* __restrict__ C       = (WHICH == 0) ? g_h1 : g_h2;

    __shared__ float As[16][68];
    __shared__ float Bs[16][BN];
    const int tid  = threadIdx.x;
    const int w    = tid >> 5;
    const int lane = tid & 31;
    const int bm   = blockIdx.x * 64;

    float acc[8][VN];
#pragma unroll
    for (int r = 0; r < 8; r++)
#pragma unroll
        for (int c = 0; c < VN; c++) acc[r][c] = 0.0f;

    for (int k0 = 0; k0 < K; k0 += 16) {
        // A tile 64x16 : clamp row so the global load is ALWAYS in-bounds
#pragma unroll
        for (int i = 0; i < 4; i++) {
            int lin = tid + i * 256;
            int m = lin >> 4, kk = lin & 15;
            int gm = bm + m;
            int gmc = (gm < M) ? gm : (M - 1);
            float v = A[(size_t)gmc * K + k0 + kk];
            As[kk][m] = (gm < M) ? v : 0.0f;
        }
#pragma unroll
        for (int i = 0; i < (16 * BN) / 256; i++) {
            int lin = tid + i * 256;
            int kk = lin / BN, n = lin % BN;
            Bs[kk][n] = B[(size_t)(k0 + kk) * N + n];
        }
        __syncthreads();
#pragma unroll
        for (int kk = 0; kk < 16; kk++) {
            float a[8], b[VN];
#pragma unroll
            for (int r = 0; r < 8; r++) a[r] = As[kk][w * 8 + r];
#pragma unroll
            for (int c = 0; c < VN; c++) b[c] = Bs[kk][lane * VN + c];
#pragma unroll
            for (int r = 0; r < 8; r++)
#pragma unroll
                for (int c = 0; c < VN; c++) acc[r][c] = fmaf(a[r], b[c], acc[r][c]);
        }
        __syncthreads();
    }
#pragma unroll
    for (int r = 0; r < 8; r++) {
        int gm = bm + w * 8 + r;
        if (gm < M) {
#pragma unroll
            for (int c = 0; c < VN; c++)
                C[(size_t)gm * N + lane * VN + c] = acc[r][c];
        }
    }
}

// ---------------- per-node attention scores, layer 1 -------------------------
__global__ __launch_bounds__(256)
void scores1_kernel(const float* __restrict__ a1s, const float* __restrict__ a1d, int Nn) {
    int idx = blockIdx.x * blockDim.x + threadIdx.x;
    if (idx >= Nn * HEADS1) return;
    int n = idx >> 3, h = idx & 7;
    const float* hp = g_h1 + (size_t)n * H1DIM + h * C1;
    float ss = 0.f, sd = 0.f;
#pragma unroll
    for (int c = 0; c < C1; c++) {
        float v = hp[c];
        ss = fmaf(v, a1s[h * C1 + c], ss);
        sd = fmaf(v, a1d[h * C1 + c], sd);
    }
    g_s1src[idx] = ss;
    g_s1dst[idx] = sd;
}

// ---------------- CSR build --------------------------------------------------
__global__ void init_deg_kernel(int Nn) {
    int i = blockIdx.x * blockDim.x + threadIdx.x;
    if (i < Nn) g_deg[i] = 1;   // self loop pre-counted
}

__global__ void histo_kernel(const void* __restrict__ ei, int E) {
    int e = blockIdx.x * blockDim.x + threadIdx.x;
    if (e < E) {
        int dst = edge_at(ei, (size_t)E + e);
        atomicAdd(&g_deg[dst], 1);
    }
}

// Block-wide Hillis-Steele scan; zero-padded low half keeps every shared read
// unconditionally in-bounds.
__global__ __launch_bounds__(1024)
void scan_kernel(int Nn) {
    __shared__ int sums[2048];
    int tid = threadIdx.x;
    int chunk = (Nn + 1023) >> 10;
    int b = tid * chunk;
    int e = min(b + chunk, Nn);
    int s = 0;
    for (int i = b; i < e; i++) s += g_deg[i];
    sums[tid] = 0;
    sums[1024 + tid] = s;
    __syncthreads();
    for (int off = 1; off < 1024; off <<= 1) {
        int v = sums[1024 + tid - off];
        __syncthreads();
        sums[1024 + tid] += v;
        __syncthreads();
    }
    int run = sums[1023 + tid];
    for (int i = b; i < e; i++) {
        g_rowptr[i] = run;
        g_cursor[i] = run;
        run += g_deg[i];
    }
    if (tid == 1023) g_rowptr[Nn] = sums[2047];
}

// scatter edges to CSR; compute layer-1 leakyrelu logits on the fly
__global__ __launch_bounds__(256)
void scatter_kernel(const void* __restrict__ ei, int E, int Nn) {
    int idx = blockIdx.x * blockDim.x + threadIdx.x;
    if (idx >= E + Nn) return;
    int src, dst;
    if (idx < E) {
        src = edge_at(ei, (size_t)idx);
        dst = edge_at(ei, (size_t)E + idx);
    } else {
        src = dst = idx - E;  // self loop
    }
    int pos = atomicAdd(&g_cursor[dst], 1);
    g_esrc[pos] = src;
    g_edst[pos] = dst;
    const float* ss = g_s1src + (size_t)src * HEADS1;
    const float* sd = g_s1dst + (size_t)dst * HEADS1;
    float* eo = g_elog + (size_t)pos * HEADS1;
#pragma unroll
    for (int h = 0; h < HEADS1; h++) {
        float v = ss[h] + sd[h];
        eo[h] = (v > 0.f) ? v : NEG_SLOPE * v;
    }
}

// ---------------- layer-1 segment softmax + aggregation (warp per node) ------
__global__ __launch_bounds__(128)
void agg1_kernel(const float* __restrict__ b1, int Nn) {
    int warp = (blockIdx.x * blockDim.x + threadIdx.x) >> 5;
    int lane = threadIdx.x & 31;
    if (warp >= Nn) return;
    int beg = g_rowptr[warp], end = g_rowptr[warp + 1];
    int h8 = lane & 7, off = lane >> 3;

    // per-head max (4 lanes cooperate per head)
    float m = -1e30f;
    for (int j = beg + off; j < end; j += 4)
        m = fmaxf(m, g_elog[(size_t)j * HEADS1 + h8]);
    m = fmaxf(m, __shfl_xor_sync(0xFFFFFFFFu, m, 8));
    m = fmaxf(m, __shfl_xor_sync(0xFFFFFFFFu, m, 16));

    // exp + per-head denom; overwrite logits with weights
    float s = 0.f;
    for (int j = beg + off; j < end; j += 4) {
        size_t a = (size_t)j * HEADS1 + h8;
        float w = __expf(g_elog[a] - m);
        g_elog[a] = w;
        s += w;
    }
    s += __shfl_xor_sync(0xFFFFFFFFu, s, 8);
    s += __shfl_xor_sync(0xFFFFFFFFu, s, 16);
    __syncwarp();

    // lane owns features c = lane + 32k ; head(c) = (lane>>4) + 2k
    float invd[4];
#pragma unroll
    for (int k = 0; k < 4; k++)
        invd[k] = 1.0f / __shfl_sync(0xFFFFFFFFu, s, (lane >> 4) + 2 * k);

    float acc[4] = {0.f, 0.f, 0.f, 0.f};
    for (int j = beg; j < end; ++j) {
        int src = g_esrc[j];
        const float* hr = g_h1 + (size_t)src * H1DIM;
        const float* wr = g_elog + (size_t)j * HEADS1;
#pragma unroll
        for (int k = 0; k < 4; k++)
            acc[k] = fmaf(wr[(lane >> 4) + 2 * k], hr[lane + 32 * k], acc[k]);
    }
#pragma unroll
    for (int k = 0; k < 4; k++) {
        int c = lane + 32 * k;
        float v = acc[k] * invd[k] + b1[c];
        g_out1[(size_t)warp * H1DIM + c] = (v > 0.f) ? v : (__expf(v) - 1.0f);  // ELU
    }
}

// ---------------- layer-2 scores (warp per node) ------------------------------
__global__ __launch_bounds__(128)
void scores2_kernel(const float* __restrict__ a2s, const float* __restrict__ a2d, int Nn) {
    int warp = (blockIdx.x * blockDim.x + threadIdx.x) >> 5;
    int lane = threadIdx.x & 31;
    if (warp >= Nn) return;
    const float* hp = g_h2 + (size_t)warp * H2DIM;
    float v0 = hp[lane], v1 = hp[lane + 32];
    float ss = v0 * a2s[lane] + v1 * a2s[lane + 32];
    float sd = v0 * a2d[lane] + v1 * a2d[lane + 32];
#pragma unroll
    for (int o = 16; o > 0; o >>= 1) {
        ss += __shfl_xor_sync(0xFFFFFFFFu, ss, o);
        sd += __shfl_xor_sync(0xFFFFFFFFu, sd, o);
    }
    if (lane == 0) {
        g_s2src[warp] = ss;
        g_s2dst[warp] = sd;
    }
}

// per-sorted-edge layer-2 logit
__global__ __launch_bounds__(256)
void edge2_kernel(int Etot) {
    int j = blockIdx.x * blockDim.x + threadIdx.x;
    if (j >= Etot) return;
    float v = g_s2src[g_esrc[j]] + g_s2dst[g_edst[j]];
    g_ew2[j] = (v > 0.f) ? v : NEG_SLOPE * v;
}

// ---------------- layer-2 softmax+agg + bias + log_softmax -> d_out ----------
__global__ __launch_bounds__(128)
void agg2_kernel(const float* __restrict__ b2, float* __restrict__ dout, int Nn) {
    int warp = (blockIdx.x * blockDim.x + threadIdx.x) >> 5;
    int lane = threadIdx.x & 31;
    if (warp >= Nn) return;
    int beg = g_rowptr[warp], end = g_rowptr[warp + 1];

    float m = -1e30f;
    for (int j = beg + lane; j < end; j += 32) m = fmaxf(m, g_ew2[j]);
#pragma unroll
    for (int o = 16; o > 0; o >>= 1) m = fmaxf(m, __shfl_xor_sync(0xFFFFFFFFu, m, o));

    float s = 0.f;
    for (int j = beg + lane; j < end; j += 32) {
        float w = __expf(g_ew2[j] - m);
        g_ew2[j] = w;
        s += w;
    }
#pragma unroll
    for (int o = 16; o > 0; o >>= 1) s += __shfl_xor_sync(0xFFFFFFFFu, s, o);
    __syncwarp();
    float inv = 1.0f / s;

    float a0 = 0.f, a1 = 0.f;
    for (int j = beg; j < end; ++j) {
        float w = g_ew2[j];
        const float* hr = g_h2 + (size_t)g_esrc[j] * H2DIM;
        a0 = fmaf(w, hr[lane], a0);
        a1 = fmaf(w, hr[lane + 32], a1);
    }
    float o0 = a0 * inv + b2[lane];
    float o1 = a1 * inv + b2[lane + 32];

    // fused log_softmax over the node's 64 outputs
    float mx = fmaxf(o0, o1);
#pragma unroll
    for (int o = 16; o > 0; o >>= 1) mx = fmaxf(mx, __shfl_xor_sync(0xFFFFFFFFu, mx, o));
    float se = __expf(o0 - mx) + __expf(o1 - mx);
#pragma unroll
    for (int o = 16; o > 0; o >>= 1) se += __shfl_xor_sync(0xFFFFFFFFu, se, o);
    float lse = __logf(se);
    dout[(size_t)warp * H2DIM + lane]      = o0 - mx - lse;
    dout[(size_t)warp * H2DIM + lane + 32] = o1 - mx - lse;
}

// ---------------- launch (pure kernel launches, default stream) --------------
extern "C" void kernel_launch(void* const* d_in, const int* in_sizes, int n_in,
                              void* d_out, int out_size) {
    const float* x   = (const float*)d_in[0];
    const void*  ei  = d_in[1];
    const float* W1  = (const float*)d_in[2];
    const float* a1s = (const float*)d_in[3];
    const float* a1d = (const float*)d_in[4];
    const float* b1  = (const float*)d_in[5];
    const float* W2  = (const float*)d_in[6];
    const float* a2s = (const float*)d_in[7];
    const float* a2d = (const float*)d_in[8];
    const float* b2  = (const float*)d_in[9];
    float*       out = (float*)d_out;

    const int Nn   = in_sizes[0] / IN_DIM;  // 50000
    const int E    = in_sizes[1] / 2;       // 800000
    const int Etot = E + Nn;

    detect_kernel<<<1, 32>>>((const int*)ei);

    // layer 1
    gemm_kernel<H1DIM, 4, 0><<<(Nn + 63) / 64, 256>>>(x, W1, Nn, IN_DIM, H1DIM);
    scores1_kernel<<<(Nn * HEADS1 + 255) / 256, 256>>>(a1s, a1d, Nn);
    init_deg_kernel<<<(Nn + 255) / 256, 256>>>(Nn);
    histo_kernel<<<(E + 255) / 256, 256>>>(ei, E);
    scan_kernel<<<1, 1024>>>(Nn);
    scatter_kernel<<<(Etot + 255) / 256, 256>>>(ei, E, Nn);
    agg1_kernel<<<(Nn + 3) / 4, 128>>>(b1, Nn);

    // layer 2
    gemm_kernel<H2DIM, 2, 1><<<(Nn + 63) / 64, 256>>>(nullptr, W2, Nn, H1DIM, H2DIM);
    scores2_kernel<<<(Nn + 3) / 4, 128>>>(a2s, a2d, Nn);
    edge2_kernel<<<(Etot + 255) / 256, 256>>>(Etot);
    agg2_kernel<<<(Nn + 3) / 4, 128>>>(b2, out, Nn);
}

// round 5
// speedup vs baseline: 1.1163x; 1.1163x over previous
#include <cuda_runtime.h>
#include <math.h>

// Problem dims (fixed by dataset)
#define MAXN 50000
#define MAXE 850000   // 800000 edges + 50000 self loops
#define IN_DIM 256
#define H1DIM 128     // 8 heads * 16
#define HEADS1 8
#define C1 16
#define H2DIM 64
#define NEG_SLOPE 0.2f

// ---------------- scratch (static device globals; no allocation) -------------
__device__ float g_h1[MAXN * H1DIM];
__device__ float g_s1src[MAXN * HEADS1];
__device__ float g_s1dst[MAXN * HEADS1];
__device__ int   g_deg[MAXN];
__device__ int   g_rowptr[MAXN + 1];
__device__ int   g_cursor[MAXN];
__device__ int   g_esrc[MAXE];
__device__ int   g_edst[MAXE];
__device__ float g_elog[MAXE * HEADS1];
__device__ float g_out1[MAXN * H1DIM];
__device__ float g_h2[MAXN * H2DIM];
__device__ float g_s2src[MAXN];
__device__ float g_s2dst[MAXN];
__device__ float g_ew2[MAXE];
__device__ int   g_is64;   // 1 if edge_index buffer is int64, 0 if int32

// ---------------- edge dtype detection --------------------------------------
__global__ void detect_kernel(const int* __restrict__ ei32) {
    if (threadIdx.x == 0 && blockIdx.x == 0) {
        int all_zero = 1;
        for (int i = 0; i < 64; i++)
            if (ei32[2 * i + 1] != 0) { all_zero = 0; break; }
        g_is64 = all_zero;
    }
}

__device__ __forceinline__ int edge_at(const void* ei, size_t idx) {
    if (g_is64) return (int)((const long long*)ei)[idx];
    return ((const int*)ei)[idx];
}

// ---------------- GEMM: C[M,N] = A[M,K] @ B[K,N] -----------------------------
// BM=128, BK=16, BN template. 256 threads, 16x16 thread grid, micro-tile 8xTN.
// WHICH==0: A = arg (x), C = g_h1.   WHICH==1: A = g_out1, C = g_h2.
template <int BN, int TN, int WHICH>
__global__ __launch_bounds__(256)
void gemm_kernel(const float* __restrict__ Aarg, const float* __restrict__ B,
                 int M, int K, int N) {
    const float* __restrict__ A = (WHICH == 0) ? Aarg : (const float*)g_out1;
    float* __restrict__ C       = (WHICH == 0) ? g_h1 : g_h2;

    __shared__ float As[16][132];   // [kk][m], padded
    __shared__ float Bs[16][BN];    // [kk][n]
    const int tid = threadIdx.x;
    const int tr  = tid >> 4;       // 0..15 (row group)
    const int tc  = tid & 15;       // 0..15 (col group)
    const int bm  = blockIdx.x * 128;

    float acc[8][TN];
#pragma unroll
    for (int r = 0; r < 8; r++)
#pragma unroll
        for (int c = 0; c < TN; c++) acc[r][c] = 0.0f;

    for (int k0 = 0; k0 < K; k0 += 16) {
        // A tile: 128 rows x 16 cols = 512 float4, 2 per thread.
#pragma unroll
        for (int i = 0; i < 2; i++) {
            int idx = tid + i * 256;
            int row = idx >> 2;            // 0..127
            int kk4 = (idx & 3) * 4;       // 0,4,8,12
            int gm = bm + row;
            int gmc = (gm < M) ? gm : (M - 1);
            float4 v = *(const float4*)(A + (size_t)gmc * K + k0 + kk4);
            if (gm >= M) v = make_float4(0.f, 0.f, 0.f, 0.f);
            As[kk4 + 0][row] = v.x;
            As[kk4 + 1][row] = v.y;
            As[kk4 + 2][row] = v.z;
            As[kk4 + 3][row] = v.w;
        }
        // B tile: 16 rows x BN cols.
#pragma unroll
        for (int i = 0; i < (16 * BN) / (4 * 256); i++) {
            int idx = tid + i * 256;
            int kk = idx / (BN / 4);
            int n4 = (idx % (BN / 4)) * 4;
            float4 v = *(const float4*)(B + (size_t)(k0 + kk) * N + n4);
            *(float4*)&Bs[kk][n4] = v;
        }
        __syncthreads();
#pragma unroll
        for (int kk = 0; kk < 16; kk++) {
            float a[8], b[TN];
            *(float4*)&a[0] = *(const float4*)&As[kk][tr * 8];
            *(float4*)&a[4] = *(const float4*)&As[kk][tr * 8 + 4];
#pragma unroll
            for (int c = 0; c < TN; c += 4)
                *(float4*)&b[c] = *(const float4*)&Bs[kk][tc * TN + c];
#pragma unroll
            for (int r = 0; r < 8; r++)
#pragma unroll
                for (int c = 0; c < TN; c++) acc[r][c] = fmaf(a[r], b[c], acc[r][c]);
        }
        __syncthreads();
    }
#pragma unroll
    for (int r = 0; r < 8; r++) {
        int gm = bm + tr * 8 + r;
        if (gm < M) {
#pragma unroll
            for (int c = 0; c < TN; c += 4)
                *(float4*)(C + (size_t)gm * N + tc * TN + c) = *(float4*)&acc[r][c];
        }
    }
}

// ---------------- per-node attention scores, layer 1 -------------------------
__global__ __launch_bounds__(256)
void scores1_kernel(const float* __restrict__ a1s, const float* __restrict__ a1d, int Nn) {
    int idx = blockIdx.x * blockDim.x + threadIdx.x;
    if (idx >= Nn * HEADS1) return;
    int n = idx >> 3, h = idx & 7;
    const float4* hp = (const float4*)(g_h1 + (size_t)n * H1DIM + h * C1);
    const float4* as = (const float4*)(a1s + h * C1);
    const float4* ad = (const float4*)(a1d + h * C1);
    float ss = 0.f, sd = 0.f;
#pragma unroll
    for (int q = 0; q < 4; q++) {
        float4 v = hp[q], s4 = as[q], d4 = ad[q];
        ss += v.x * s4.x + v.y * s4.y + v.z * s4.z + v.w * s4.w;
        sd += v.x * d4.x + v.y * d4.y + v.z * d4.z + v.w * d4.w;
    }
    g_s1src[idx] = ss;
    g_s1dst[idx] = sd;
}

// ---------------- CSR build --------------------------------------------------
__global__ void init_deg_kernel(int Nn) {
    int i = blockIdx.x * blockDim.x + threadIdx.x;
    if (i < Nn) g_deg[i] = 1;   // self loop pre-counted
}

__global__ void histo_kernel(const void* __restrict__ ei, int E) {
    int e = blockIdx.x * blockDim.x + threadIdx.x;
    if (e < E) {
        int dst = edge_at(ei, (size_t)E + e);
        atomicAdd(&g_deg[dst], 1);
    }
}

__global__ __launch_bounds__(1024)
void scan_kernel(int Nn) {
    __shared__ int sums[2048];
    int tid = threadIdx.x;
    int chunk = (Nn + 1023) >> 10;
    int b = tid * chunk;
    int e = min(b + chunk, Nn);
    int s = 0;
    for (int i = b; i < e; i++) s += g_deg[i];
    sums[tid] = 0;
    sums[1024 + tid] = s;
    __syncthreads();
    for (int off = 1; off < 1024; off <<= 1) {
        int v = sums[1024 + tid - off];
        __syncthreads();
        sums[1024 + tid] += v;
        __syncthreads();
    }
    int run = sums[1023 + tid];
    for (int i = b; i < e; i++) {
        g_rowptr[i] = run;
        g_cursor[i] = run;
        run += g_deg[i];
    }
    if (tid == 1023) g_rowptr[Nn] = sums[2047];
}

// scatter edges to CSR; compute layer-1 leakyrelu logits on the fly
__global__ __launch_bounds__(256)
void scatter_kernel(const void* __restrict__ ei, int E, int Nn) {
    int idx = blockIdx.x * blockDim.x + threadIdx.x;
    if (idx >= E + Nn) return;
    int src, dst;
    if (idx < E) {
        src = edge_at(ei, (size_t)idx);
        dst = edge_at(ei, (size_t)E + idx);
    } else {
        src = dst = idx - E;  // self loop
    }
    int pos = atomicAdd(&g_cursor[dst], 1);
    g_esrc[pos] = src;
    g_edst[pos] = dst;
    const float* ss = g_s1src + (size_t)src * HEADS1;
    const float* sd = g_s1dst + (size_t)dst * HEADS1;
    float* eo = g_elog + (size_t)pos * HEADS1;
#pragma unroll
    for (int h = 0; h < HEADS1; h++) {
        float v = ss[h] + sd[h];
        eo[h] = (v > 0.f) ? v : NEG_SLOPE * v;
    }
}

// ---------------- layer-1 segment softmax + aggregation (warp per node) ------
// Lane owns features [lane*4, lane*4+4) = one float4 of the 128-wide row.
// All 4 features live in head (lane>>2).
__global__ __launch_bounds__(256)
void agg1_kernel(const float* __restrict__ b1, int Nn) {
    int warp = (blockIdx.x * blockDim.x + threadIdx.x) >> 5;
    int lane = threadIdx.x & 31;
    if (warp >= Nn) return;
    int beg = g_rowptr[warp], end = g_rowptr[warp + 1];
    int h8 = lane & 7, off = lane >> 3;

    // per-head max (4 lanes cooperate per head)
    float m = -1e30f;
    for (int j = beg + off; j < end; j += 4)
        m = fmaxf(m, g_elog[(size_t)j * HEADS1 + h8]);
    m = fmaxf(m, __shfl_xor_sync(0xFFFFFFFFu, m, 8));
    m = fmaxf(m, __shfl_xor_sync(0xFFFFFFFFu, m, 16));

    // exp + per-head denom; overwrite logits with weights
    float s = 0.f;
    for (int j = beg + off; j < end; j += 4) {
        size_t a = (size_t)j * HEADS1 + h8;
        float w = __expf(g_elog[a] - m);
        g_elog[a] = w;
        s += w;
    }
    s += __shfl_xor_sync(0xFFFFFFFFu, s, 8);
    s += __shfl_xor_sync(0xFFFFFFFFu, s, 16);
    __syncwarp();

    const int head = lane >> 2;                       // head of this lane's float4
    float inv = 1.0f / __shfl_sync(0xFFFFFFFFu, s, head);

    float4 acc = make_float4(0.f, 0.f, 0.f, 0.f);
    int j = beg;
    for (; j + 1 < end; j += 2) {
        int s0 = g_esrc[j], s1 = g_esrc[j + 1];
        float w0 = g_elog[(size_t)j * HEADS1 + head];
        float w1 = g_elog[(size_t)(j + 1) * HEADS1 + head];
        float4 v0 = *(const float4*)(g_h1 + (size_t)s0 * H1DIM + lane * 4);
        float4 v1 = *(const float4*)(g_h1 + (size_t)s1 * H1DIM + lane * 4);
        acc.x = fmaf(w0, v0.x, acc.x); acc.y = fmaf(w0, v0.y, acc.y);
        acc.z = fmaf(w0, v0.z, acc.z); acc.w = fmaf(w0, v0.w, acc.w);
        acc.x = fmaf(w1, v1.x, acc.x); acc.y = fmaf(w1, v1.y, acc.y);
        acc.z = fmaf(w1, v1.z, acc.z); acc.w = fmaf(w1, v1.w, acc.w);
    }
    if (j < end) {
        int s0 = g_esrc[j];
        float w0 = g_elog[(size_t)j * HEADS1 + head];
        float4 v0 = *(const float4*)(g_h1 + (size_t)s0 * H1DIM + lane * 4);
        acc.x = fmaf(w0, v0.x, acc.x); acc.y = fmaf(w0, v0.y, acc.y);
        acc.z = fmaf(w0, v0.z, acc.z); acc.w = fmaf(w0, v0.w, acc.w);
    }

    float4 bb = *(const float4*)(b1 + lane * 4);
    float4 o;
    o.x = acc.x * inv + bb.x;  o.y = acc.y * inv + bb.y;
    o.z = acc.z * inv + bb.z;  o.w = acc.w * inv + bb.w;
    o.x = (o.x > 0.f) ? o.x : (__expf(o.x) - 1.0f);
    o.y = (o.y > 0.f) ? o.y : (__expf(o.y) - 1.0f);
    o.z = (o.z > 0.f) ? o.z : (__expf(o.z) - 1.0f);
    o.w = (o.w > 0.f) ? o.w : (__expf(o.w) - 1.0f);
    *(float4*)(g_out1 + (size_t)warp * H1DIM + lane * 4) = o;
}

// ---------------- layer-2 scores (warp per node) ------------------------------
__global__ __launch_bounds__(256)
void scores2_kernel(const float* __restrict__ a2s, const float* __restrict__ a2d, int Nn) {
    int warp = (blockIdx.x * blockDim.x + threadIdx.x) >> 5;
    int lane = threadIdx.x & 31;
    if (warp >= Nn) return;
    const float2 v = *(const float2*)(g_h2 + (size_t)warp * H2DIM + lane * 2);
    const float2 s2 = *(const float2*)(a2s + lane * 2);
    const float2 d2 = *(const float2*)(a2d + lane * 2);
    float ss = v.x * s2.x + v.y * s2.y;
    float sd = v.x * d2.x + v.y * d2.y;
#pragma unroll
    for (int o = 16; o > 0; o >>= 1) {
        ss += __shfl_xor_sync(0xFFFFFFFFu, ss, o);
        sd += __shfl_xor_sync(0xFFFFFFFFu, sd, o);
    }
    if (lane == 0) {
        g_s2src[warp] = ss;
        g_s2dst[warp] = sd;
    }
}

// per-sorted-edge layer-2 logit
__global__ __launch_bounds__(256)
void edge2_kernel(int Etot) {
    int j = blockIdx.x * blockDim.x + threadIdx.x;
    if (j >= Etot) return;
    float v = g_s2src[g_esrc[j]] + g_s2dst[g_edst[j]];
    g_ew2[j] = (v > 0.f) ? v : NEG_SLOPE * v;
}

// ---------------- layer-2 softmax+agg + bias + log_softmax -> d_out ----------
// Lane owns features [lane*2, lane*2+2) of the 64-wide row.
__global__ __launch_bounds__(256)
void agg2_kernel(const float* __restrict__ b2, float* __restrict__ dout, int Nn) {
    int warp = (blockIdx.x * blockDim.x + threadIdx.x) >> 5;
    int lane = threadIdx.x & 31;
    if (warp >= Nn) return;
    int beg = g_rowptr[warp], end = g_rowptr[warp + 1];

    float m = -1e30f;
    for (int j = beg + lane; j < end; j += 32) m = fmaxf(m, g_ew2[j]);
#pragma unroll
    for (int o = 16; o > 0; o >>= 1) m = fmaxf(m, __shfl_xor_sync(0xFFFFFFFFu, m, o));

    float s = 0.f;
    for (int j = beg + lane; j < end; j += 32) {
        float w = __expf(g_ew2[j] - m);
        g_ew2[j] = w;
        s += w;
    }
#pragma unroll
    for (int o = 16; o > 0; o >>= 1) s += __shfl_xor_sync(0xFFFFFFFFu, s, o);
    __syncwarp();
    float inv = 1.0f / s;

    float a0 = 0.f, a1 = 0.f;
    int j = beg;
    for (; j + 1 < end; j += 2) {
        float w0 = g_ew2[j], w1 = g_ew2[j + 1];
        float2 v0 = *(const float2*)(g_h2 + (size_t)g_esrc[j] * H2DIM + lane * 2);
        float2 v1 = *(const float2*)(g_h2 + (size_t)g_esrc[j + 1] * H2DIM + lane * 2);
        a0 = fmaf(w0, v0.x, a0); a1 = fmaf(w0, v0.y, a1);
        a0 = fmaf(w1, v1.x, a0); a1 = fmaf(w1, v1.y, a1);
    }
    if (j < end) {
        float w0 = g_ew2[j];
        float2 v0 = *(const float2*)(g_h2 + (size_t)g_esrc[j] * H2DIM + lane * 2);
        a0 = fmaf(w0, v0.x, a0); a1 = fmaf(w0, v0.y, a1);
    }
    float2 bb = *(const float2*)(b2 + lane * 2);
    float o0 = a0 * inv + bb.x;
    float o1 = a1 * inv + bb.y;

    // fused log_softmax over the node's 64 outputs
    float mx = fmaxf(o0, o1);
#pragma unroll
    for (int o = 16; o > 0; o >>= 1) mx = fmaxf(mx, __shfl_xor_sync(0xFFFFFFFFu, mx, o));
    float se = __expf(o0 - mx) + __expf(o1 - mx);
#pragma unroll
    for (int o = 16; o > 0; o >>= 1) se += __shfl_xor_sync(0xFFFFFFFFu, se, o);
    float lse = __logf(se);
    float2 r;  r.x = o0 - mx - lse;  r.y = o1 - mx - lse;
    *(float2*)(dout + (size_t)warp * H2DIM + lane * 2) = r;
}

// ---------------- launch (pure kernel launches, default stream) --------------
extern "C" void kernel_launch(void* const* d_in, const int* in_sizes, int n_in,
                              void* d_out, int out_size) {
    const float* x   = (const float*)d_in[0];
    const void*  ei  = d_in[1];
    const float* W1  = (const float*)d_in[2];
    const float* a1s = (const float*)d_in[3];
    const float* a1d = (const float*)d_in[4];
    const float* b1  = (const float*)d_in[5];
    const float* W2  = (const float*)d_in[6];
    const float* a2s = (const float*)d_in[7];
    const float* a2d = (const float*)d_in[8];
    const float* b2  = (const float*)d_in[9];
    float*       out = (float*)d_out;

    const int Nn   = in_sizes[0] / IN_DIM;  // 50000
    const int E    = in_sizes[1] / 2;       // 800000
    const int Etot = E + Nn;

    detect_kernel<<<1, 32>>>((const int*)ei);

    // layer 1
    gemm_kernel<H1DIM, 8, 0><<<(Nn + 127) / 128, 256>>>(x, W1, Nn, IN_DIM, H1DIM);
    scores1_kernel<<<(Nn * HEADS1 + 255) / 256, 256>>>(a1s, a1d, Nn);
    init_deg_kernel<<<(Nn + 255) / 256, 256>>>(Nn);
    histo_kernel<<<(E + 255) / 256, 256>>>(ei, E);
    scan_kernel<<<1, 1024>>>(Nn);
    scatter_kernel<<<(Etot + 255) / 256, 256>>>(ei, E, Nn);
    agg1_kernel<<<(Nn + 7) / 8, 256>>>(b1, Nn);

    // layer 2
    gemm_kernel<H2DIM, 4, 1><<<(Nn + 127) / 128, 256>>>(nullptr, W2, Nn, H1DIM, H2DIM);
    scores2_kernel<<<(Nn + 7) / 8, 256>>>(a2s, a2d, Nn);
    edge2_kernel<<<(Etot + 255) / 256, 256>>>(Etot);
    agg2_kernel<<<(Nn + 7) / 8, 256>>>(b2, out, Nn);
}

// round 6
// speedup vs baseline: 1.4805x; 1.3262x over previous
#include <cuda_runtime.h>
#include <math.h>

// Problem dims (fixed by dataset)
#define MAXN 50000
#define MAXE 850000   // 800000 edges + 50000 self loops
#define IN_DIM 256
#define H1DIM 128     // 8 heads * 16
#define HEADS1 8
#define H2DIM 64
#define NEG_SLOPE 0.2f

// ---------------- scratch (static device globals; no allocation) -------------
__device__ float g_h1[MAXN * H1DIM];
__device__ float g_s1src[MAXN * HEADS1];
__device__ float g_s1dst[MAXN * HEADS1];
__device__ int   g_deg[MAXN];
__device__ int   g_rowptr[MAXN + 1];
__device__ int   g_cursor[MAXN];
__device__ int   g_esrc[MAXE];
__device__ float g_out1[MAXN * H1DIM];
__device__ float g_h2[MAXN * H2DIM];
__device__ float g_s2src[MAXN];
__device__ float g_s2dst[MAXN];
__device__ int   g_is64;   // 1 if edge_index buffer is int64, 0 if int32

// ---------------- helpers -----------------------------------------------------
__device__ __forceinline__ int edge_at(const void* ei, size_t idx) {
    if (g_is64) return (int)((const long long*)ei)[idx];
    return ((const int*)ei)[idx];
}

__device__ __forceinline__ float to_tf32(float x) {
    float r;
    asm("cvt.rna.tf32.f32 %0, %1;" : "=f"(r) : "f"(x));
    return r;
}

__device__ __forceinline__ void mma_tf32(float* d, const unsigned* a,
                                         unsigned b0, unsigned b1) {
    asm volatile(
        "mma.sync.aligned.m16n8k8.row.col.f32.tf32.tf32.f32 "
        "{%0,%1,%2,%3}, {%4,%5,%6,%7}, {%8,%9}, {%0,%1,%2,%3};"
        : "+f"(d[0]), "+f"(d[1]), "+f"(d[2]), "+f"(d[3])
        : "r"(a[0]), "r"(a[1]), "r"(a[2]), "r"(a[3]), "r"(b0), "r"(b1));
}

// ---------------- init: deg=1 everywhere + edge-dtype detect ------------------
__global__ void init_kernel(const int* __restrict__ ei32, int Nn) {
    int i = blockIdx.x * blockDim.x + threadIdx.x;
    if (i < Nn) g_deg[i] = 1;   // self loop pre-counted
    if (i == 0) {
        int all_zero = 1;
        for (int k = 0; k < 64; k++)
            if (ei32[2 * k + 1] != 0) { all_zero = 0; break; }
        g_is64 = all_zero;
    }
}

// ---------------- tf32 tensor-core GEMM: C[M,BN] = A[M,K] @ B[K,BN] ----------
// Block tile 128 x BN (BN covers full N). 256 threads.
// BN=128: warp grid 4x2, warp tile 32x64 (2 m-atoms). BN=64: 8x1, 16x64 (1 m-atom).
// WHICH==0: A = arg (x), C = g_h1.  WHICH==1: A = g_out1, C = g_h2.
template <int BN, int WHICH>
__global__ __launch_bounds__(256)
void gemm_tf32(const float* __restrict__ Aarg, const float* __restrict__ B,
               int M, int K) {
    const float* __restrict__ A = (WHICH == 0) ? Aarg : (const float*)g_out1;
    float* __restrict__ C       = (WHICH == 0) ? g_h1 : g_h2;

    constexpr int KB   = 32;
    constexpr int NW_N = BN / 64;       // warps along N
    constexpr int WM   = 128 / (8 / NW_N);  // 32 or 16
    constexpr int MAT  = WM / 16;       // 2 or 1
    constexpr int NAT  = 8;             // 64/8 atoms along N per warp

    __shared__ float As[128][36];       // [m][k], conflict-free frag reads
    __shared__ float Bs[KB][BN + 4];    // [k][n]

    const int tid  = threadIdx.x;
    const int wid  = tid >> 5;
    const int lane = tid & 31;
    const int wm   = (wid / NW_N) * WM;
    const int wn   = (wid % NW_N) * 64;
    const int bm   = blockIdx.x * 128;
    const int lq   = lane & 3;          // quad index
    const int lg   = lane >> 2;         // group index 0..7

    float acc[MAT][NAT][4];
#pragma unroll
    for (int i = 0; i < MAT; i++)
#pragma unroll
        for (int j = 0; j < NAT; j++)
#pragma unroll
            for (int c = 0; c < 4; c++) acc[i][j][c] = 0.0f;

    for (int k0 = 0; k0 < K; k0 += KB) {
        // A tile: 128 x 32 floats = 1024 float4, 4 per thread
#pragma unroll
        for (int i = 0; i < 4; i++) {
            int idx = tid + i * 256;
            int row = idx >> 3;
            int kc  = (idx & 7) * 4;
            int gm  = bm + row;
            int gmc = (gm < M) ? gm : (M - 1);
            float4 v = *(const float4*)(A + (size_t)gmc * K + k0 + kc);
            if (gm >= M) v = make_float4(0.f, 0.f, 0.f, 0.f);
            v.x = to_tf32(v.x); v.y = to_tf32(v.y);
            v.z = to_tf32(v.z); v.w = to_tf32(v.w);
            *(float4*)&As[row][kc] = v;
        }
        // B tile: 32 x BN floats
#pragma unroll
        for (int i = 0; i < (KB * BN) / (4 * 256); i++) {
            int idx = tid + i * 256;
            int kk  = idx / (BN / 4);
            int nc  = (idx % (BN / 4)) * 4;
            float4 v = *(const float4*)(B + (size_t)(k0 + kk) * BN + nc);
            v.x = to_tf32(v.x); v.y = to_tf32(v.y);
            v.z = to_tf32(v.z); v.w = to_tf32(v.w);
            *(float4*)&Bs[kk][nc] = v;
        }
        __syncthreads();
#pragma unroll
        for (int ks = 0; ks < KB; ks += 8) {
            unsigned a[MAT][4];
#pragma unroll
            for (int i = 0; i < MAT; i++) {
                int m0 = wm + i * 16;
                a[i][0] = __float_as_uint(As[m0 + lg][ks + lq]);
                a[i][1] = __float_as_uint(As[m0 + lg + 8][ks + lq]);
                a[i][2] = __float_as_uint(As[m0 + lg][ks + lq + 4]);
                a[i][3] = __float_as_uint(As[m0 + lg + 8][ks + lq + 4]);
            }
#pragma unroll
            for (int j = 0; j < NAT; j++) {
                unsigned b0 = __float_as_uint(Bs[ks + lq][wn + j * 8 + lg]);
                unsigned b1 = __float_as_uint(Bs[ks + lq + 4][wn + j * 8 + lg]);
#pragma unroll
                for (int i = 0; i < MAT; i++) mma_tf32(acc[i][j], a[i], b0, b1);
            }
        }
        __syncthreads();
    }
    // epilogue: c0,c1 -> (m, 2q), (m, 2q+1); c2,c3 -> (m+8, ...)
#pragma unroll
    for (int i = 0; i < MAT; i++) {
#pragma unroll
        for (int j = 0; j < NAT; j++) {
            int gm = bm + wm + i * 16 + lg;
            int n0 = wn + j * 8 + 2 * lq;
            if (gm < M)
                *(float2*)(C + (size_t)gm * BN + n0) =
                    make_float2(acc[i][j][0], acc[i][j][1]);
            if (gm + 8 < M)
                *(float2*)(C + (size_t)(gm + 8) * BN + n0) =
                    make_float2(acc[i][j][2], acc[i][j][3]);
        }
    }
}

// ---------------- per-node attention scores, layer 1 -------------------------
__global__ __launch_bounds__(256)
void scores1_kernel(const float* __restrict__ a1s, const float* __restrict__ a1d, int Nn) {
    int idx = blockIdx.x * blockDim.x + threadIdx.x;
    if (idx >= Nn * HEADS1) return;
    int n = idx >> 3, h = idx & 7;
    const float4* hp = (const float4*)(g_h1 + (size_t)n * H1DIM + h * 16);
    const float4* as = (const float4*)(a1s + h * 16);
    const float4* ad = (const float4*)(a1d + h * 16);
    float ss = 0.f, sd = 0.f;
#pragma unroll
    for (int q = 0; q < 4; q++) {
        float4 v = hp[q], s4 = as[q], d4 = ad[q];
        ss += v.x * s4.x + v.y * s4.y + v.z * s4.z + v.w * s4.w;
        sd += v.x * d4.x + v.y * d4.y + v.z * d4.z + v.w * d4.w;
    }
    g_s1src[idx] = ss;
    g_s1dst[idx] = sd;
}

// ---------------- CSR build --------------------------------------------------
__global__ void histo_kernel(const void* __restrict__ ei, int E) {
    int e = blockIdx.x * blockDim.x + threadIdx.x;
    if (e < E) atomicAdd(&g_deg[edge_at(ei, (size_t)E + e)], 1);
}

__global__ __launch_bounds__(1024)
void scan_kernel(int Nn) {
    __shared__ int sums[2048];
    int tid = threadIdx.x;
    int chunk = (Nn + 1023) >> 10;
    int b = tid * chunk;
    int e = min(b + chunk, Nn);
    int s = 0;
    for (int i = b; i < e; i++) s += g_deg[i];
    sums[tid] = 0;
    sums[1024 + tid] = s;
    __syncthreads();
    for (int off = 1; off < 1024; off <<= 1) {
        int v = sums[1024 + tid - off];
        __syncthreads();
        sums[1024 + tid] += v;
        __syncthreads();
    }
    int run = sums[1023 + tid];
    for (int i = b; i < e; i++) {
        g_rowptr[i] = run;
        g_cursor[i] = run;
        run += g_deg[i];
    }
    if (tid == 1023) g_rowptr[Nn] = sums[2047];
}

// scatter edges to CSR (src list only; logits recomputed on the fly later)
__global__ __launch_bounds__(256)
void scatter_kernel(const void* __restrict__ ei, int E, int Nn) {
    int idx = blockIdx.x * blockDim.x + threadIdx.x;
    if (idx >= E + Nn) return;
    int src, dst;
    if (idx < E) {
        src = edge_at(ei, (size_t)idx);
        dst = edge_at(ei, (size_t)E + idx);
    } else {
        src = dst = idx - E;  // self loop
    }
    int pos = atomicAdd(&g_cursor[dst], 1);
    g_esrc[pos] = src;
}

// ---------------- layer-1 segment softmax + aggregation (warp per node) ------
// Lane owns features [lane*4, lane*4+4); head = lane>>2. Logits recomputed
// from s1src gather + per-head dst constant (no stored edge weights).
__global__ __launch_bounds__(256)
void agg1_kernel(const float* __restrict__ b1, int Nn) {
    int warp = (blockIdx.x * blockDim.x + threadIdx.x) >> 5;
    int lane = threadIdx.x & 31;
    if (warp >= Nn) return;
    int beg = g_rowptr[warp], end = g_rowptr[warp + 1];
    const int head = lane >> 2;
    const int q    = lane & 3;
    const float sdst = g_s1dst[(size_t)warp * HEADS1 + head];

    // pass 1: per-head max (4 lanes per head)
    float m = -1e30f;
    for (int j = beg + q; j < end; j += 4) {
        int src = g_esrc[j];
        float v = g_s1src[(size_t)src * HEADS1 + head] + sdst;
        v = (v > 0.f) ? v : NEG_SLOPE * v;
        m = fmaxf(m, v);
    }
    m = fmaxf(m, __shfl_xor_sync(0xFFFFFFFFu, m, 1));
    m = fmaxf(m, __shfl_xor_sync(0xFFFFFFFFu, m, 2));

    // pass 2: fused denom + weighted feature aggregation
    float4 acc = make_float4(0.f, 0.f, 0.f, 0.f);
    float s = 0.f;
    int j = beg;
    for (; j + 1 < end; j += 2) {
        int s0 = g_esrc[j], s1 = g_esrc[j + 1];
        float v0 = g_s1src[(size_t)s0 * HEADS1 + head] + sdst;
        float v1 = g_s1src[(size_t)s1 * HEADS1 + head] + sdst;
        v0 = (v0 > 0.f) ? v0 : NEG_SLOPE * v0;
        v1 = (v1 > 0.f) ? v1 : NEG_SLOPE * v1;
        float w0 = __expf(v0 - m), w1 = __expf(v1 - m);
        s += w0 + w1;
        float4 h0 = *(const float4*)(g_h1 + (size_t)s0 * H1DIM + lane * 4);
        float4 h1 = *(const float4*)(g_h1 + (size_t)s1 * H1DIM + lane * 4);
        acc.x = fmaf(w0, h0.x, acc.x); acc.y = fmaf(w0, h0.y, acc.y);
        acc.z = fmaf(w0, h0.z, acc.z); acc.w = fmaf(w0, h0.w, acc.w);
        acc.x = fmaf(w1, h1.x, acc.x); acc.y = fmaf(w1, h1.y, acc.y);
        acc.z = fmaf(w1, h1.z, acc.z); acc.w = fmaf(w1, h1.w, acc.w);
    }
    if (j < end) {
        int s0 = g_esrc[j];
        float v0 = g_s1src[(size_t)s0 * HEADS1 + head] + sdst;
        v0 = (v0 > 0.f) ? v0 : NEG_SLOPE * v0;
        float w0 = __expf(v0 - m);
        s += w0;
        float4 h0 = *(const float4*)(g_h1 + (size_t)s0 * H1DIM + lane * 4);
        acc.x = fmaf(w0, h0.x, acc.x); acc.y = fmaf(w0, h0.y, acc.y);
        acc.z = fmaf(w0, h0.z, acc.z); acc.w = fmaf(w0, h0.w, acc.w);
    }
    float inv = 1.0f / s;   // deg >= 1 (self loop) so s > 0
    float4 bb = *(const float4*)(b1 + lane * 4);
    float4 o;
    o.x = acc.x * inv + bb.x;  o.y = acc.y * inv + bb.y;
    o.z = acc.z * inv + bb.z;  o.w = acc.w * inv + bb.w;
    o.x = (o.x > 0.f) ? o.x : (__expf(o.x) - 1.0f);
    o.y = (o.y > 0.f) ? o.y : (__expf(o.y) - 1.0f);
    o.z = (o.z > 0.f) ? o.z : (__expf(o.z) - 1.0f);
    o.w = (o.w > 0.f) ? o.w : (__expf(o.w) - 1.0f);
    *(float4*)(g_out1 + (size_t)warp * H1DIM + lane * 4) = o;
}

// ---------------- layer-2 scores (warp per node) ------------------------------
__global__ __launch_bounds__(256)
void scores2_kernel(const float* __restrict__ a2s, const float* __restrict__ a2d, int Nn) {
    int warp = (blockIdx.x * blockDim.x + threadIdx.x) >> 5;
    int lane = threadIdx.x & 31;
    if (warp >= Nn) return;
    const float2 v  = *(const float2*)(g_h2 + (size_t)warp * H2DIM + lane * 2);
    const float2 s2 = *(const float2*)(a2s + lane * 2);
    const float2 d2 = *(const float2*)(a2d + lane * 2);
    float ss = v.x * s2.x + v.y * s2.y;
    float sd = v.x * d2.x + v.y * d2.y;
#pragma unroll
    for (int o = 16; o > 0; o >>= 1) {
        ss += __shfl_xor_sync(0xFFFFFFFFu, ss, o);
        sd += __shfl_xor_sync(0xFFFFFFFFu, sd, o);
    }
    if (lane == 0) {
        g_s2src[warp] = ss;
        g_s2dst[warp] = sd;
    }
}

// ---------------- layer-2 softmax+agg + bias + log_softmax -> d_out ----------
// Logits recomputed from s2src gather + dst constant.
__global__ __launch_bounds__(256)
void agg2_kernel(const float* __restrict__ b2, float* __restrict__ dout, int Nn) {
    int warp = (blockIdx.x * blockDim.x + threadIdx.x) >> 5;
    int lane = threadIdx.x & 31;
    if (warp >= Nn) return;
    int beg = g_rowptr[warp], end = g_rowptr[warp + 1];
    const float sdst = g_s2dst[warp];

    float m = -1e30f;
    for (int j = beg + lane; j < end; j += 32) {
        float v = g_s2src[g_esrc[j]] + sdst;
        v = (v > 0.f) ? v : NEG_SLOPE * v;
        m = fmaxf(m, v);
    }
#pragma unroll
    for (int o = 16; o > 0; o >>= 1) m = fmaxf(m, __shfl_xor_sync(0xFFFFFFFFu, m, o));

    float a0 = 0.f, a1 = 0.f, s = 0.f;
    int j = beg;
    for (; j + 1 < end; j += 2) {
        int s0 = g_esrc[j], s1 = g_esrc[j + 1];
        float v0 = g_s2src[s0] + sdst, v1 = g_s2src[s1] + sdst;
        v0 = (v0 > 0.f) ? v0 : NEG_SLOPE * v0;
        v1 = (v1 > 0.f) ? v1 : NEG_SLOPE * v1;
        float w0 = __expf(v0 - m), w1 = __expf(v1 - m);
        s += w0 + w1;
        float2 h0 = *(const float2*)(g_h2 + (size_t)s0 * H2DIM + lane * 2);
        float2 h1 = *(const float2*)(g_h2 + (size_t)s1 * H2DIM + lane * 2);
        a0 = fmaf(w0, h0.x, a0); a1 = fmaf(w0, h0.y, a1);
        a0 = fmaf(w1, h1.x, a0); a1 = fmaf(w1, h1.y, a1);
    }
    if (j < end) {
        int s0 = g_esrc[j];
        float v0 = g_s2src[s0] + sdst;
        v0 = (v0 > 0.f) ? v0 : NEG_SLOPE * v0;
        float w0 = __expf(v0 - m);
        s += w0;
        float2 h0 = *(const float2*)(g_h2 + (size_t)s0 * H2DIM + lane * 2);
        a0 = fmaf(w0, h0.x, a0); a1 = fmaf(w0, h0.y, a1);
    }
    float inv = 1.0f / s;
    float2 bb = *(const float2*)(b2 + lane * 2);
    float o0 = a0 * inv + bb.x;
    float o1 = a1 * inv + bb.y;

    float mx = fmaxf(o0, o1);
#pragma unroll
    for (int o = 16; o > 0; o >>= 1) mx = fmaxf(mx, __shfl_xor_sync(0xFFFFFFFFu, mx, o));
    float se = __expf(o0 - mx) + __expf(o1 - mx);
#pragma unroll
    for (int o = 16; o > 0; o >>= 1) se += __shfl_xor_sync(0xFFFFFFFFu, se, o);
    float lse = __logf(se);
    float2 r;  r.x = o0 - mx - lse;  r.y = o1 - mx - lse;
    *(float2*)(dout + (size_t)warp * H2DIM + lane * 2) = r;
}

// ---------------- launch (pure kernel launches, default stream) --------------
extern "C" void kernel_launch(void* const* d_in, const int* in_sizes, int n_in,
                              void* d_out, int out_size) {
    const float* x   = (const float*)d_in[0];
    const void*  ei  = d_in[1];
    const float* W1  = (const float*)d_in[2];
    const float* a1s = (const float*)d_in[3];
    const float* a1d = (const float*)d_in[4];
    const float* b1  = (const float*)d_in[5];
    const float* W2  = (const float*)d_in[6];
    const float* a2s = (const float*)d_in[7];
    const float* a2d = (const float*)d_in[8];
    const float* b2  = (const float*)d_in[9];
    float*       out = (float*)d_out;

    const int Nn   = in_sizes[0] / IN_DIM;  // 50000
    const int E    = in_sizes[1] / 2;       // 800000
    const int Etot = E + Nn;

    init_kernel<<<(Nn + 255) / 256, 256>>>((const int*)ei, Nn);

    // layer 1
    gemm_tf32<H1DIM, 0><<<(Nn + 127) / 128, 256>>>(x, W1, Nn, IN_DIM);
    scores1_kernel<<<(Nn * HEADS1 + 255) / 256, 256>>>(a1s, a1d, Nn);
    histo_kernel<<<(E + 255) / 256, 256>>>(ei, E);
    scan_kernel<<<1, 1024>>>(Nn);
    scatter_kernel<<<(Etot + 255) / 256, 256>>>(ei, E, Nn);
    agg1_kernel<<<(Nn + 7) / 8, 256>>>(b1, Nn);

    // layer 2
    gemm_tf32<H2DIM, 1><<<(Nn + 127) / 128, 256>>>(nullptr, W2, Nn, H1DIM);
    scores2_kernel<<<(Nn + 7) / 8, 256>>>(a2s, a2d, Nn);
    agg2_kernel<<<(Nn + 7) / 8, 256>>>(b2, out, Nn);
}

// round 7
// speedup vs baseline: 1.5302x; 1.0335x over previous
#include <cuda_runtime.h>
#include <math.h>

// Problem dims (fixed by dataset)
#define MAXN 50000
#define MAXE 850000   // 800000 edges + 50000 self loops
#define IN_DIM 256
#define H1DIM 128     // 8 heads * 16
#define HEADS1 8
#define H2DIM 64
#define NEG_SLOPE 0.2f

// ---------------- scratch (static device globals; no allocation) -------------
__device__ float g_h1[MAXN * H1DIM];
__device__ float g_s1src[MAXN * HEADS1];
__device__ float g_s1dst[MAXN * HEADS1];
__device__ int   g_deg[MAXN];
__device__ int   g_rowptr[MAXN + 1];
__device__ int   g_cursor[MAXN];
__device__ int   g_esrc[MAXE];
__device__ float g_out1[MAXN * H1DIM];
__device__ float g_h2[MAXN * H2DIM];
__device__ float g_s2src[MAXN];
__device__ float g_s2dst[MAXN];
__device__ int   g_is64;   // 1 if edge_index buffer is int64, 0 if int32

// ---------------- helpers -----------------------------------------------------
__device__ __forceinline__ int edge_at(const void* ei, size_t idx) {
    if (g_is64) return (int)((const long long*)ei)[idx];
    return ((const int*)ei)[idx];
}

__device__ __forceinline__ float to_tf32(float x) {
    float r;
    asm("cvt.rna.tf32.f32 %0, %1;" : "=f"(r) : "f"(x));
    return r;
}

__device__ __forceinline__ float lrelu(float v) {
    return (v > 0.f) ? v : NEG_SLOPE * v;
}

__device__ __forceinline__ void mma_tf32(float* d, const unsigned* a,
                                         unsigned b0, unsigned b1) {
    asm volatile(
        "mma.sync.aligned.m16n8k8.row.col.f32.tf32.tf32.f32 "
        "{%0,%1,%2,%3}, {%4,%5,%6,%7}, {%8,%9}, {%0,%1,%2,%3};"
        : "+f"(d[0]), "+f"(d[1]), "+f"(d[2]), "+f"(d[3])
        : "r"(a[0]), "r"(a[1]), "r"(a[2]), "r"(a[3]), "r"(b0), "r"(b1));
}

// ---------------- init: deg=1 everywhere + edge-dtype detect ------------------
__global__ void init_kernel(const int* __restrict__ ei32, int Nn) {
    int i = blockIdx.x * blockDim.x + threadIdx.x;
    if (i < Nn) g_deg[i] = 1;   // self loop pre-counted
    if (i == 0) {
        int all_zero = 1;
        for (int k = 0; k < 64; k++)
            if (ei32[2 * k + 1] != 0) { all_zero = 0; break; }
        g_is64 = all_zero;
    }
}

// ---------------- tf32 tensor-core GEMM: C[M,BN] = A[M,K] @ B[K,BN] ----------
template <int BN, int WHICH>
__global__ __launch_bounds__(256)
void gemm_tf32(const float* __restrict__ Aarg, const float* __restrict__ B,
               int M, int K) {
    const float* __restrict__ A = (WHICH == 0) ? Aarg : (const float*)g_out1;
    float* __restrict__ C       = (WHICH == 0) ? g_h1 : g_h2;

    constexpr int KB   = 32;
    constexpr int NW_N = BN / 64;
    constexpr int WM   = 128 / (8 / NW_N);
    constexpr int MAT  = WM / 16;
    constexpr int NAT  = 8;

    __shared__ float As[128][36];
    __shared__ float Bs[KB][BN + 4];

    const int tid  = threadIdx.x;
    const int wid  = tid >> 5;
    const int lane = tid & 31;
    const int wm   = (wid / NW_N) * WM;
    const int wn   = (wid % NW_N) * 64;
    const int bm   = blockIdx.x * 128;
    const int lq   = lane & 3;
    const int lg   = lane >> 2;

    float acc[MAT][NAT][4];
#pragma unroll
    for (int i = 0; i < MAT; i++)
#pragma unroll
        for (int j = 0; j < NAT; j++)
#pragma unroll
            for (int c = 0; c < 4; c++) acc[i][j][c] = 0.0f;

    for (int k0 = 0; k0 < K; k0 += KB) {
#pragma unroll
        for (int i = 0; i < 4; i++) {
            int idx = tid + i * 256;
            int row = idx >> 3;
            int kc  = (idx & 7) * 4;
            int gm  = bm + row;
            int gmc = (gm < M) ? gm : (M - 1);
            float4 v = *(const float4*)(A + (size_t)gmc * K + k0 + kc);
            if (gm >= M) v = make_float4(0.f, 0.f, 0.f, 0.f);
            v.x = to_tf32(v.x); v.y = to_tf32(v.y);
            v.z = to_tf32(v.z); v.w = to_tf32(v.w);
            *(float4*)&As[row][kc] = v;
        }
#pragma unroll
        for (int i = 0; i < (KB * BN) / (4 * 256); i++) {
            int idx = tid + i * 256;
            int kk  = idx / (BN / 4);
            int nc  = (idx % (BN / 4)) * 4;
            float4 v = *(const float4*)(B + (size_t)(k0 + kk) * BN + nc);
            v.x = to_tf32(v.x); v.y = to_tf32(v.y);
            v.z = to_tf32(v.z); v.w = to_tf32(v.w);
            *(float4*)&Bs[kk][nc] = v;
        }
        __syncthreads();
#pragma unroll
        for (int ks = 0; ks < KB; ks += 8) {
            unsigned a[MAT][4];
#pragma unroll
            for (int i = 0; i < MAT; i++) {
                int m0 = wm + i * 16;
                a[i][0] = __float_as_uint(As[m0 + lg][ks + lq]);
                a[i][1] = __float_as_uint(As[m0 + lg + 8][ks + lq]);
                a[i][2] = __float_as_uint(As[m0 + lg][ks + lq + 4]);
                a[i][3] = __float_as_uint(As[m0 + lg + 8][ks + lq + 4]);
            }
#pragma unroll
            for (int j = 0; j < NAT; j++) {
                unsigned b0 = __float_as_uint(Bs[ks + lq][wn + j * 8 + lg]);
                unsigned b1 = __float_as_uint(Bs[ks + lq + 4][wn + j * 8 + lg]);
#pragma unroll
                for (int i = 0; i < MAT; i++) mma_tf32(acc[i][j], a[i], b0, b1);
            }
        }
        __syncthreads();
    }
#pragma unroll
    for (int i = 0; i < MAT; i++) {
#pragma unroll
        for (int j = 0; j < NAT; j++) {
            int gm = bm + wm + i * 16 + lg;
            int n0 = wn + j * 8 + 2 * lq;
            if (gm < M)
                *(float2*)(C + (size_t)gm * BN + n0) =
                    make_float2(acc[i][j][0], acc[i][j][1]);
            if (gm + 8 < M)
                *(float2*)(C + (size_t)(gm + 8) * BN + n0) =
                    make_float2(acc[i][j][2], acc[i][j][3]);
        }
    }
}

// ---------------- per-node attention scores, layer 1 -------------------------
__global__ __launch_bounds__(256)
void scores1_kernel(const float* __restrict__ a1s, const float* __restrict__ a1d, int Nn) {
    int idx = blockIdx.x * blockDim.x + threadIdx.x;
    if (idx >= Nn * HEADS1) return;
    int n = idx >> 3, h = idx & 7;
    const float4* hp = (const float4*)(g_h1 + (size_t)n * H1DIM + h * 16);
    const float4* as = (const float4*)(a1s + h * 16);
    const float4* ad = (const float4*)(a1d + h * 16);
    float ss = 0.f, sd = 0.f;
#pragma unroll
    for (int q = 0; q < 4; q++) {
        float4 v = hp[q], s4 = as[q], d4 = ad[q];
        ss += v.x * s4.x + v.y * s4.y + v.z * s4.z + v.w * s4.w;
        sd += v.x * d4.x + v.y * d4.y + v.z * d4.z + v.w * d4.w;
    }
    g_s1src[idx] = ss;
    g_s1dst[idx] = sd;
}

// ---------------- CSR build --------------------------------------------------
__global__ void histo_kernel(const void* __restrict__ ei, int E) {
    int e = blockIdx.x * blockDim.x + threadIdx.x;
    if (e < E) atomicAdd(&g_deg[edge_at(ei, (size_t)E + e)], 1);
}

__global__ __launch_bounds__(1024)
void scan_kernel(int Nn) {
    __shared__ int sums[2048];
    int tid = threadIdx.x;
    int chunk = (Nn + 1023) >> 10;
    int b = tid * chunk;
    int e = min(b + chunk, Nn);
    int s = 0;
    for (int i = b; i < e; i++) s += g_deg[i];
    sums[tid] = 0;
    sums[1024 + tid] = s;
    __syncthreads();
    for (int off = 1; off < 1024; off <<= 1) {
        int v = sums[1024 + tid - off];
        __syncthreads();
        sums[1024 + tid] += v;
        __syncthreads();
    }
    int run = sums[1023 + tid];
    for (int i = b; i < e; i++) {
        g_rowptr[i] = run;
        g_cursor[i] = run;
        run += g_deg[i];
    }
    if (tid == 1023) g_rowptr[Nn] = sums[2047];
}

// scatter edges to CSR (src list only; logits recomputed on the fly later)
__global__ __launch_bounds__(256)
void scatter_kernel(const void* __restrict__ ei, int E, int Nn) {
    int idx = blockIdx.x * blockDim.x + threadIdx.x;
    if (idx >= E + Nn) return;
    int src, dst;
    if (idx < E) {
        src = edge_at(ei, (size_t)idx);
        dst = edge_at(ei, (size_t)E + idx);
    } else {
        src = dst = idx - E;  // self loop
    }
    int pos = atomicAdd(&g_cursor[dst], 1);
    g_esrc[pos] = src;
}

// ---------------- layer-1 softmax+agg, single pass, warp per node -----------
// alpha = exp(e)/sum(exp(e)) — max subtraction dropped (|e| <~ 12, safe in fp32).
// Lane owns features [lane*4, lane*4+4); head = lane>>2.
__global__ __launch_bounds__(256)
void agg1_kernel(const float* __restrict__ b1, int Nn) {
    int warp = (blockIdx.x * blockDim.x + threadIdx.x) >> 5;
    int lane = threadIdx.x & 31;
    if (warp >= Nn) return;
    int beg = g_rowptr[warp], end = g_rowptr[warp + 1];
    const int head = lane >> 2;
    const float sdst = g_s1dst[(size_t)warp * HEADS1 + head];

    float4 acc = make_float4(0.f, 0.f, 0.f, 0.f);
    float s = 0.f;
    int j = beg;
    for (; j + 3 < end; j += 4) {
        int i0 = g_esrc[j],     i1 = g_esrc[j + 1];
        int i2 = g_esrc[j + 2], i3 = g_esrc[j + 3];
        float w0 = __expf(lrelu(g_s1src[(size_t)i0 * HEADS1 + head] + sdst));
        float w1 = __expf(lrelu(g_s1src[(size_t)i1 * HEADS1 + head] + sdst));
        float w2 = __expf(lrelu(g_s1src[(size_t)i2 * HEADS1 + head] + sdst));
        float w3 = __expf(lrelu(g_s1src[(size_t)i3 * HEADS1 + head] + sdst));
        float4 h0 = *(const float4*)(g_h1 + (size_t)i0 * H1DIM + lane * 4);
        float4 h1 = *(const float4*)(g_h1 + (size_t)i1 * H1DIM + lane * 4);
        float4 h2 = *(const float4*)(g_h1 + (size_t)i2 * H1DIM + lane * 4);
        float4 h3 = *(const float4*)(g_h1 + (size_t)i3 * H1DIM + lane * 4);
        s += (w0 + w1) + (w2 + w3);
        acc.x = fmaf(w0, h0.x, acc.x); acc.y = fmaf(w0, h0.y, acc.y);
        acc.z = fmaf(w0, h0.z, acc.z); acc.w = fmaf(w0, h0.w, acc.w);
        acc.x = fmaf(w1, h1.x, acc.x); acc.y = fmaf(w1, h1.y, acc.y);
        acc.z = fmaf(w1, h1.z, acc.z); acc.w = fmaf(w1, h1.w, acc.w);
        acc.x = fmaf(w2, h2.x, acc.x); acc.y = fmaf(w2, h2.y, acc.y);
        acc.z = fmaf(w2, h2.z, acc.z); acc.w = fmaf(w2, h2.w, acc.w);
        acc.x = fmaf(w3, h3.x, acc.x); acc.y = fmaf(w3, h3.y, acc.y);
        acc.z = fmaf(w3, h3.z, acc.z); acc.w = fmaf(w3, h3.w, acc.w);
    }
    for (; j < end; ++j) {
        int i0 = g_esrc[j];
        float w0 = __expf(lrelu(g_s1src[(size_t)i0 * HEADS1 + head] + sdst));
        float4 h0 = *(const float4*)(g_h1 + (size_t)i0 * H1DIM + lane * 4);
        s += w0;
        acc.x = fmaf(w0, h0.x, acc.x); acc.y = fmaf(w0, h0.y, acc.y);
        acc.z = fmaf(w0, h0.z, acc.z); acc.w = fmaf(w0, h0.w, acc.w);
    }
    float inv = 1.0f / s;   // deg >= 1 so s > 0
    float4 bb = *(const float4*)(b1 + lane * 4);
    float4 o;
    o.x = acc.x * inv + bb.x;  o.y = acc.y * inv + bb.y;
    o.z = acc.z * inv + bb.z;  o.w = acc.w * inv + bb.w;
    o.x = (o.x > 0.f) ? o.x : (__expf(o.x) - 1.0f);
    o.y = (o.y > 0.f) ? o.y : (__expf(o.y) - 1.0f);
    o.z = (o.z > 0.f) ? o.z : (__expf(o.z) - 1.0f);
    o.w = (o.w > 0.f) ? o.w : (__expf(o.w) - 1.0f);
    *(float4*)(g_out1 + (size_t)warp * H1DIM + lane * 4) = o;
}

// ---------------- layer-2 scores (warp per node) ------------------------------
__global__ __launch_bounds__(256)
void scores2_kernel(const float* __restrict__ a2s, const float* __restrict__ a2d, int Nn) {
    int warp = (blockIdx.x * blockDim.x + threadIdx.x) >> 5;
    int lane = threadIdx.x & 31;
    if (warp >= Nn) return;
    const float2 v  = *(const float2*)(g_h2 + (size_t)warp * H2DIM + lane * 2);
    const float2 s2 = *(const float2*)(a2s + lane * 2);
    const float2 d2 = *(const float2*)(a2d + lane * 2);
    float ss = v.x * s2.x + v.y * s2.y;
    float sd = v.x * d2.x + v.y * d2.y;
#pragma unroll
    for (int o = 16; o > 0; o >>= 1) {
        ss += __shfl_xor_sync(0xFFFFFFFFu, ss, o);
        sd += __shfl_xor_sync(0xFFFFFFFFu, sd, o);
    }
    if (lane == 0) {
        g_s2src[warp] = ss;
        g_s2dst[warp] = sd;
    }
}

// ---------------- layer-2 softmax+agg + bias + log_softmax -> d_out ----------
__global__ __launch_bounds__(256)
void agg2_kernel(const float* __restrict__ b2, float* __restrict__ dout, int Nn) {
    int warp = (blockIdx.x * blockDim.x + threadIdx.x) >> 5;
    int lane = threadIdx.x & 31;
    if (warp >= Nn) return;
    int beg = g_rowptr[warp], end = g_rowptr[warp + 1];
    const float sdst = g_s2dst[warp];

    float a0 = 0.f, a1 = 0.f, s = 0.f;
    int j = beg;
    for (; j + 3 < end; j += 4) {
        int i0 = g_esrc[j],     i1 = g_esrc[j + 1];
        int i2 = g_esrc[j + 2], i3 = g_esrc[j + 3];
        float w0 = __expf(lrelu(g_s2src[i0] + sdst));
        float w1 = __expf(lrelu(g_s2src[i1] + sdst));
        float w2 = __expf(lrelu(g_s2src[i2] + sdst));
        float w3 = __expf(lrelu(g_s2src[i3] + sdst));
        float2 h0 = *(const float2*)(g_h2 + (size_t)i0 * H2DIM + lane * 2);
        float2 h1 = *(const float2*)(g_h2 + (size_t)i1 * H2DIM + lane * 2);
        float2 h2 = *(const float2*)(g_h2 + (size_t)i2 * H2DIM + lane * 2);
        float2 h3 = *(const float2*)(g_h2 + (size_t)i3 * H2DIM + lane * 2);
        s += (w0 + w1) + (w2 + w3);
        a0 = fmaf(w0, h0.x, a0); a1 = fmaf(w0, h0.y, a1);
        a0 = fmaf(w1, h1.x, a0); a1 = fmaf(w1, h1.y, a1);
        a0 = fmaf(w2, h2.x, a0); a1 = fmaf(w2, h2.y, a1);
        a0 = fmaf(w3, h3.x, a0); a1 = fmaf(w3, h3.y, a1);
    }
    for (; j < end; ++j) {
        int i0 = g_esrc[j];
        float w0 = __expf(lrelu(g_s2src[i0] + sdst));
        float2 h0 = *(const float2*)(g_h2 + (size_t)i0 * H2DIM + lane * 2);
        s += w0;
        a0 = fmaf(w0, h0.x, a0); a1 = fmaf(w0, h0.y, a1);
    }
    float inv = 1.0f / s;
    float2 bb = *(const float2*)(b2 + lane * 2);
    float o0 = a0 * inv + bb.x;
    float o1 = a1 * inv + bb.y;

    // fused log_softmax over the node's 64 outputs
    float mx = fmaxf(o0, o1);
#pragma unroll
    for (int o = 16; o > 0; o >>= 1) mx = fmaxf(mx, __shfl_xor_sync(0xFFFFFFFFu, mx, o));
    float se = __expf(o0 - mx) + __expf(o1 - mx);
#pragma unroll
    for (int o = 16; o > 0; o >>= 1) se += __shfl_xor_sync(0xFFFFFFFFu, se, o);
    float lse = __logf(se);
    float2 r;  r.x = o0 - mx - lse;  r.y = o1 - mx - lse;
    *(float2*)(dout + (size_t)warp * H2DIM + lane * 2) = r;
}

// ---------------- launch (pure kernel launches, default stream) --------------
extern "C" void kernel_launch(void* const* d_in, const int* in_sizes, int n_in,
                              void* d_out, int out_size) {
    const float* x   = (const float*)d_in[0];
    const void*  ei  = d_in[1];
    const float* W1  = (const float*)d_in[2];
    const float* a1s = (const float*)d_in[3];
    const float* a1d = (const float*)d_in[4];
    const float* b1  = (const float*)d_in[5];
    const float* W2  = (const float*)d_in[6];
    const float* a2s = (const float*)d_in[7];
    const float* a2d = (const float*)d_in[8];
    const float* b2  = (const float*)d_in[9];
    float*       out = (float*)d_out;

    const int Nn   = in_sizes[0] / IN_DIM;  // 50000
    const int E    = in_sizes[1] / 2;       // 800000
    const int Etot = E + Nn;

    init_kernel<<<(Nn + 255) / 256, 256>>>((const int*)ei, Nn);

    // layer 1
    gemm_tf32<H1DIM, 0><<<(Nn + 127) / 128, 256>>>(x, W1, Nn, IN_DIM);
    scores1_kernel<<<(Nn * HEADS1 + 255) / 256, 256>>>(a1s, a1d, Nn);
    histo_kernel<<<(E + 255) / 256, 256>>>(ei, E);
    scan_kernel<<<1, 1024>>>(Nn);
    scatter_kernel<<<(Etot + 255) / 256, 256>>>(ei, E, Nn);
    agg1_kernel<<<(Nn + 7) / 8, 256>>>(b1, Nn);

    // layer 2
    gemm_tf32<H2DIM, 1><<<(Nn + 127) / 128, 256>>>(nullptr, W2, Nn, H1DIM);
    scores2_kernel<<<(Nn + 7) / 8, 256>>>(a2s, a2d, Nn);
    agg2_kernel<<<(Nn + 7) / 8, 256>>>(b2, out, Nn);
}

// round 8
// speedup vs baseline: 1.8090x; 1.1823x over previous
#include <cuda_runtime.h>
#include <cuda_fp16.h>
#include <math.h>

// Problem dims (fixed by dataset)
#define MAXN 50000
#define MAXE 850000   // 800000 edges + 50000 self loops
#define IN_DIM 256
#define H1DIM 128     // 8 heads * 16
#define HEADS1 8
#define H2DIM 64
#define NEG_SLOPE 0.2f

// ---------------- scratch (static device globals; no allocation) -------------
__device__ float  g_h1[MAXN * H1DIM];     // fp32 (for scores1)
__device__ __half g_h1h[MAXN * H1DIM];    // fp16 mirror (for agg1 gather)
__device__ float  g_s1src[MAXN * HEADS1];
__device__ float  g_s1dst[MAXN * HEADS1];
__device__ int    g_deg[MAXN];
__device__ int    g_rowptr[MAXN + 1];
__device__ int    g_cursor[MAXN];
__device__ int    g_esrc[MAXE];
__device__ float  g_out1[MAXN * H1DIM];
__device__ float  g_h2[MAXN * H2DIM];     // fp32 (for scores2)
__device__ __half g_h2h[MAXN * H2DIM];    // fp16 mirror (for agg2 gather)
__device__ float  g_s2src[MAXN];
__device__ float  g_s2dst[MAXN];
__device__ int    g_is64;

// ---------------- helpers -----------------------------------------------------
__device__ __forceinline__ int edge_at(const void* ei, size_t idx) {
    if (g_is64) return (int)((const long long*)ei)[idx];
    return ((const int*)ei)[idx];
}

__device__ __forceinline__ float to_tf32(float x) {
    float r;
    asm("cvt.rna.tf32.f32 %0, %1;" : "=f"(r) : "f"(x));
    return r;
}

__device__ __forceinline__ float lrelu(float v) {
    return (v > 0.f) ? v : NEG_SLOPE * v;
}

__device__ __forceinline__ void mma_tf32(float* d, const unsigned* a,
                                         unsigned b0, unsigned b1) {
    asm volatile(
        "mma.sync.aligned.m16n8k8.row.col.f32.tf32.tf32.f32 "
        "{%0,%1,%2,%3}, {%4,%5,%6,%7}, {%8,%9}, {%0,%1,%2,%3};"
        : "+f"(d[0]), "+f"(d[1]), "+f"(d[2]), "+f"(d[3])
        : "r"(a[0]), "r"(a[1]), "r"(a[2]), "r"(a[3]), "r"(b0), "r"(b1));
}

// ---------------- init: deg=1 everywhere + edge-dtype detect ------------------
__global__ void init_kernel(const int* __restrict__ ei32, int Nn) {
    int i = blockIdx.x * blockDim.x + threadIdx.x;
    if (i < Nn) g_deg[i] = 1;   // self loop pre-counted
    if (i == 0) {
        int all_zero = 1;
        for (int k = 0; k < 64; k++)
            if (ei32[2 * k + 1] != 0) { all_zero = 0; break; }
        g_is64 = all_zero;
    }
}

// ---------------- tf32 tensor-core GEMM body ----------------------------------
// Block tile 128 x BN; 256 threads. Writes fp32 C and fp16 mirror Ch.
// WHICH==0: A=arg(x), C=g_h1/g_h1h.  WHICH==1: A=g_out1, C=g_h2/g_h2h.
template <int BN, int WHICH>
__device__ __forceinline__ void gemm_body(const float* __restrict__ Aarg,
                                          const float* __restrict__ B,
                                          int M, int K, int bidx) {
    const float* __restrict__ A = (WHICH == 0) ? Aarg : (const float*)g_out1;
    float*  __restrict__ C  = (WHICH == 0) ? g_h1  : g_h2;
    __half* __restrict__ Ch = (WHICH == 0) ? g_h1h : g_h2h;

    constexpr int KB   = 32;
    constexpr int NW_N = BN / 64;
    constexpr int WM   = 128 / (8 / NW_N);
    constexpr int MAT  = WM / 16;
    constexpr int NAT  = 8;

    __shared__ float As[128][36];
    __shared__ float Bs[KB][BN + 4];

    const int tid  = threadIdx.x;
    const int wid  = tid >> 5;
    const int lane = tid & 31;
    const int wm   = (wid / NW_N) * WM;
    const int wn   = (wid % NW_N) * 64;
    const int bm   = bidx * 128;
    const int lq   = lane & 3;
    const int lg   = lane >> 2;

    float acc[MAT][NAT][4];
#pragma unroll
    for (int i = 0; i < MAT; i++)
#pragma unroll
        for (int j = 0; j < NAT; j++)
#pragma unroll
            for (int c = 0; c < 4; c++) acc[i][j][c] = 0.0f;

    for (int k0 = 0; k0 < K; k0 += KB) {
#pragma unroll
        for (int i = 0; i < 4; i++) {
            int idx = tid + i * 256;
            int row = idx >> 3;
            int kc  = (idx & 7) * 4;
            int gm  = bm + row;
            int gmc = (gm < M) ? gm : (M - 1);
            float4 v = *(const float4*)(A + (size_t)gmc * K + k0 + kc);
            if (gm >= M) v = make_float4(0.f, 0.f, 0.f, 0.f);
            v.x = to_tf32(v.x); v.y = to_tf32(v.y);
            v.z = to_tf32(v.z); v.w = to_tf32(v.w);
            *(float4*)&As[row][kc] = v;
        }
#pragma unroll
        for (int i = 0; i < (KB * BN) / (4 * 256); i++) {
            int idx = tid + i * 256;
            int kk  = idx / (BN / 4);
            int nc  = (idx % (BN / 4)) * 4;
            float4 v = *(const float4*)(B + (size_t)(k0 + kk) * BN + nc);
            v.x = to_tf32(v.x); v.y = to_tf32(v.y);
            v.z = to_tf32(v.z); v.w = to_tf32(v.w);
            *(float4*)&Bs[kk][nc] = v;
        }
        __syncthreads();
#pragma unroll
        for (int ks = 0; ks < KB; ks += 8) {
            unsigned a[MAT][4];
#pragma unroll
            for (int i = 0; i < MAT; i++) {
                int m0 = wm + i * 16;
                a[i][0] = __float_as_uint(As[m0 + lg][ks + lq]);
                a[i][1] = __float_as_uint(As[m0 + lg + 8][ks + lq]);
                a[i][2] = __float_as_uint(As[m0 + lg][ks + lq + 4]);
                a[i][3] = __float_as_uint(As[m0 + lg + 8][ks + lq + 4]);
            }
#pragma unroll
            for (int j = 0; j < NAT; j++) {
                unsigned b0 = __float_as_uint(Bs[ks + lq][wn + j * 8 + lg]);
                unsigned b1 = __float_as_uint(Bs[ks + lq + 4][wn + j * 8 + lg]);
#pragma unroll
                for (int i = 0; i < MAT; i++) mma_tf32(acc[i][j], a[i], b0, b1);
            }
        }
        __syncthreads();
    }
#pragma unroll
    for (int i = 0; i < MAT; i++) {
#pragma unroll
        for (int j = 0; j < NAT; j++) {
            int gm = bm + wm + i * 16 + lg;
            int n0 = wn + j * 8 + 2 * lq;
            if (gm < M) {
                *(float2*)(C + (size_t)gm * BN + n0) =
                    make_float2(acc[i][j][0], acc[i][j][1]);
                *(__half2*)(Ch + (size_t)gm * BN + n0) =
                    __floats2half2_rn(acc[i][j][0], acc[i][j][1]);
            }
            if (gm + 8 < M) {
                *(float2*)(C + (size_t)(gm + 8) * BN + n0) =
                    make_float2(acc[i][j][2], acc[i][j][3]);
                *(__half2*)(Ch + (size_t)(gm + 8) * BN + n0) =
                    __floats2half2_rn(acc[i][j][2], acc[i][j][3]);
            }
        }
    }
}

// ---------------- K1: gemm1 blocks || histo blocks ----------------------------
__global__ __launch_bounds__(256)
void k1_gemm1_histo(const float* __restrict__ x, const float* __restrict__ W1,
                    const void* __restrict__ ei, int M, int E, int nGemmBlocks) {
    if ((int)blockIdx.x < nGemmBlocks) {
        gemm_body<H1DIM, 0>(x, W1, M, IN_DIM, blockIdx.x);
    } else {
        int e = (blockIdx.x - nGemmBlocks) * 256 + threadIdx.x;
        if (e < E) atomicAdd(&g_deg[edge_at(ei, (size_t)E + e)], 1);
    }
}

// ---------------- scan (1 block) ----------------------------------------------
__global__ __launch_bounds__(1024)
void scan_kernel(int Nn) {
    __shared__ int sums[2048];
    int tid = threadIdx.x;
    int chunk = (Nn + 1023) >> 10;
    int b = tid * chunk;
    int e = min(b + chunk, Nn);
    int s = 0;
    for (int i = b; i < e; i++) s += g_deg[i];
    sums[tid] = 0;
    sums[1024 + tid] = s;
    __syncthreads();
    for (int off = 1; off < 1024; off <<= 1) {
        int v = sums[1024 + tid - off];
        __syncthreads();
        sums[1024 + tid] += v;
        __syncthreads();
    }
    int run = sums[1023 + tid];
    for (int i = b; i < e; i++) {
        g_rowptr[i] = run;
        g_cursor[i] = run;
        run += g_deg[i];
    }
    if (tid == 1023) g_rowptr[Nn] = sums[2047];
}

// ---------------- K2: scores1 blocks || scatter blocks -------------------------
__global__ __launch_bounds__(256)
void k2_scores1_scatter(const float* __restrict__ a1s, const float* __restrict__ a1d,
                        const void* __restrict__ ei, int Nn, int E, int nScoreBlocks) {
    if ((int)blockIdx.x < nScoreBlocks) {
        int idx = blockIdx.x * 256 + threadIdx.x;
        if (idx >= Nn * HEADS1) return;
        int n = idx >> 3, h = idx & 7;
        const float4* hp = (const float4*)(g_h1 + (size_t)n * H1DIM + h * 16);
        const float4* as = (const float4*)(a1s + h * 16);
        const float4* ad = (const float4*)(a1d + h * 16);
        float ss = 0.f, sd = 0.f;
#pragma unroll
        for (int q = 0; q < 4; q++) {
            float4 v = hp[q], s4 = as[q], d4 = ad[q];
            ss += v.x * s4.x + v.y * s4.y + v.z * s4.z + v.w * s4.w;
            sd += v.x * d4.x + v.y * d4.y + v.z * d4.z + v.w * d4.w;
        }
        g_s1src[idx] = ss;
        g_s1dst[idx] = sd;
    } else {
        int idx = (blockIdx.x - nScoreBlocks) * 256 + threadIdx.x;
        if (idx >= E + Nn) return;
        int src, dst;
        if (idx < E) {
            src = edge_at(ei, (size_t)idx);
            dst = edge_at(ei, (size_t)E + idx);
        } else {
            src = dst = idx - E;  // self loop
        }
        int pos = atomicAdd(&g_cursor[dst], 1);
        g_esrc[pos] = src;
    }
}

// ---------------- layer-1 softmax+agg (fp16 gather), warp per node ------------
__global__ __launch_bounds__(256)
void agg1_kernel(const float* __restrict__ b1, int Nn) {
    int warp = (blockIdx.x * blockDim.x + threadIdx.x) >> 5;
    int lane = threadIdx.x & 31;
    if (warp >= Nn) return;
    int beg = g_rowptr[warp], end = g_rowptr[warp + 1];
    const int head = lane >> 2;
    const float sdst = g_s1dst[(size_t)warp * HEADS1 + head];

    float4 acc = make_float4(0.f, 0.f, 0.f, 0.f);
    float s = 0.f;
    int j = beg;
    for (; j + 3 < end; j += 4) {
        int i0 = g_esrc[j],     i1 = g_esrc[j + 1];
        int i2 = g_esrc[j + 2], i3 = g_esrc[j + 3];
        float w0 = __expf(lrelu(g_s1src[(size_t)i0 * HEADS1 + head] + sdst));
        float w1 = __expf(lrelu(g_s1src[(size_t)i1 * HEADS1 + head] + sdst));
        float w2 = __expf(lrelu(g_s1src[(size_t)i2 * HEADS1 + head] + sdst));
        float w3 = __expf(lrelu(g_s1src[(size_t)i3 * HEADS1 + head] + sdst));
        uint2 u0 = *(const uint2*)(g_h1h + (size_t)i0 * H1DIM + lane * 4);
        uint2 u1 = *(const uint2*)(g_h1h + (size_t)i1 * H1DIM + lane * 4);
        uint2 u2 = *(const uint2*)(g_h1h + (size_t)i2 * H1DIM + lane * 4);
        uint2 u3 = *(const uint2*)(g_h1h + (size_t)i3 * H1DIM + lane * 4);
        s += (w0 + w1) + (w2 + w3);
        float2 p, q;
        p = __half22float2(*(__half2*)&u0.x); q = __half22float2(*(__half2*)&u0.y);
        acc.x = fmaf(w0, p.x, acc.x); acc.y = fmaf(w0, p.y, acc.y);
        acc.z = fmaf(w0, q.x, acc.z); acc.w = fmaf(w0, q.y, acc.w);
        p = __half22float2(*(__half2*)&u1.x); q = __half22float2(*(__half2*)&u1.y);
        acc.x = fmaf(w1, p.x, acc.x); acc.y = fmaf(w1, p.y, acc.y);
        acc.z = fmaf(w1, q.x, acc.z); acc.w = fmaf(w1, q.y, acc.w);
        p = __half22float2(*(__half2*)&u2.x); q = __half22float2(*(__half2*)&u2.y);
        acc.x = fmaf(w2, p.x, acc.x); acc.y = fmaf(w2, p.y, acc.y);
        acc.z = fmaf(w2, q.x, acc.z); acc.w = fmaf(w2, q.y, acc.w);
        p = __half22float2(*(__half2*)&u3.x); q = __half22float2(*(__half2*)&u3.y);
        acc.x = fmaf(w3, p.x, acc.x); acc.y = fmaf(w3, p.y, acc.y);
        acc.z = fmaf(w3, q.x, acc.z); acc.w = fmaf(w3, q.y, acc.w);
    }
    for (; j < end; ++j) {
        int i0 = g_esrc[j];
        float w0 = __expf(lrelu(g_s1src[(size_t)i0 * HEADS1 + head] + sdst));
        uint2 u0 = *(const uint2*)(g_h1h + (size_t)i0 * H1DIM + lane * 4);
        s += w0;
        float2 p = __half22float2(*(__half2*)&u0.x);
        float2 q = __half22float2(*(__half2*)&u0.y);
        acc.x = fmaf(w0, p.x, acc.x); acc.y = fmaf(w0, p.y, acc.y);
        acc.z = fmaf(w0, q.x, acc.z); acc.w = fmaf(w0, q.y, acc.w);
    }
    float inv = 1.0f / s;
    float4 bb = *(const float4*)(b1 + lane * 4);
    float4 o;
    o.x = acc.x * inv + bb.x;  o.y = acc.y * inv + bb.y;
    o.z = acc.z * inv + bb.z;  o.w = acc.w * inv + bb.w;
    o.x = (o.x > 0.f) ? o.x : (__expf(o.x) - 1.0f);
    o.y = (o.y > 0.f) ? o.y : (__expf(o.y) - 1.0f);
    o.z = (o.z > 0.f) ? o.z : (__expf(o.z) - 1.0f);
    o.w = (o.w > 0.f) ? o.w : (__expf(o.w) - 1.0f);
    *(float4*)(g_out1 + (size_t)warp * H1DIM + lane * 4) = o;
}

// ---------------- gemm2 (standalone) ------------------------------------------
__global__ __launch_bounds__(256)
void gemm2_kernel(const float* __restrict__ W2, int M) {
    gemm_body<H2DIM, 1>(nullptr, W2, M, H1DIM, blockIdx.x);
}

// ---------------- layer-2 scores (warp per node) -------------------------------
__global__ __launch_bounds__(256)
void scores2_kernel(const float* __restrict__ a2s, const float* __restrict__ a2d, int Nn) {
    int warp = (blockIdx.x * blockDim.x + threadIdx.x) >> 5;
    int lane = threadIdx.x & 31;
    if (warp >= Nn) return;
    const float2 v  = *(const float2*)(g_h2 + (size_t)warp * H2DIM + lane * 2);
    const float2 s2 = *(const float2*)(a2s + lane * 2);
    const float2 d2 = *(const float2*)(a2d + lane * 2);
    float ss = v.x * s2.x + v.y * s2.y;
    float sd = v.x * d2.x + v.y * d2.y;
#pragma unroll
    for (int o = 16; o > 0; o >>= 1) {
        ss += __shfl_xor_sync(0xFFFFFFFFu, ss, o);
        sd += __shfl_xor_sync(0xFFFFFFFFu, sd, o);
    }
    if (lane == 0) {
        g_s2src[warp] = ss;
        g_s2dst[warp] = sd;
    }
}

// ---------------- layer-2 softmax+agg (fp16 gather) + log_softmax -> d_out ----
__global__ __launch_bounds__(256)
void agg2_kernel(const float* __restrict__ b2, float* __restrict__ dout, int Nn) {
    int warp = (blockIdx.x * blockDim.x + threadIdx.x) >> 5;
    int lane = threadIdx.x & 31;
    if (warp >= Nn) return;
    int beg = g_rowptr[warp], end = g_rowptr[warp + 1];
    const float sdst = g_s2dst[warp];

    float a0 = 0.f, a1 = 0.f, s = 0.f;
    int j = beg;
    for (; j + 3 < end; j += 4) {
        int i0 = g_esrc[j],     i1 = g_esrc[j + 1];
        int i2 = g_esrc[j + 2], i3 = g_esrc[j + 3];
        float w0 = __expf(lrelu(g_s2src[i0] + sdst));
        float w1 = __expf(lrelu(g_s2src[i1] + sdst));
        float w2 = __expf(lrelu(g_s2src[i2] + sdst));
        float w3 = __expf(lrelu(g_s2src[i3] + sdst));
        __half2 u0 = *(const __half2*)(g_h2h + (size_t)i0 * H2DIM + lane * 2);
        __half2 u1 = *(const __half2*)(g_h2h + (size_t)i1 * H2DIM + lane * 2);
        __half2 u2 = *(const __half2*)(g_h2h + (size_t)i2 * H2DIM + lane * 2);
        __half2 u3 = *(const __half2*)(g_h2h + (size_t)i3 * H2DIM + lane * 2);
        s += (w0 + w1) + (w2 + w3);
        float2 f;
        f = __half22float2(u0); a0 = fmaf(w0, f.x, a0); a1 = fmaf(w0, f.y, a1);
        f = __half22float2(u1); a0 = fmaf(w1, f.x, a0); a1 = fmaf(w1, f.y, a1);
        f = __half22float2(u2); a0 = fmaf(w2, f.x, a0); a1 = fmaf(w2, f.y, a1);
        f = __half22float2(u3); a0 = fmaf(w3, f.x, a0); a1 = fmaf(w3, f.y, a1);
    }
    for (; j < end; ++j) {
        int i0 = g_esrc[j];
        float w0 = __expf(lrelu(g_s2src[i0] + sdst));
        __half2 u0 = *(const __half2*)(g_h2h + (size_t)i0 * H2DIM + lane * 2);
        s += w0;
        float2 f = __half22float2(u0);
        a0 = fmaf(w0, f.x, a0); a1 = fmaf(w0, f.y, a1);
    }
    float inv = 1.0f / s;
    float2 bb = *(const float2*)(b2 + lane * 2);
    float o0 = a0 * inv + bb.x;
    float o1 = a1 * inv + bb.y;

    // fused log_softmax over the node's 64 outputs
    float mx = fmaxf(o0, o1);
#pragma unroll
    for (int o = 16; o > 0; o >>= 1) mx = fmaxf(mx, __shfl_xor_sync(0xFFFFFFFFu, mx, o));
    float se = __expf(o0 - mx) + __expf(o1 - mx);
#pragma unroll
    for (int o = 16; o > 0; o >>= 1) se += __shfl_xor_sync(0xFFFFFFFFu, se, o);
    float lse = __logf(se);
    float2 r;  r.x = o0 - mx - lse;  r.y = o1 - mx - lse;
    *(float2*)(dout + (size_t)warp * H2DIM + lane * 2) = r;
}

// ---------------- launch (pure kernel launches, default stream) --------------
extern "C" void kernel_launch(void* const* d_in, const int* in_sizes, int n_in,
                              void* d_out, int out_size) {
    const float* x   = (const float*)d_in[0];
    const void*  ei  = d_in[1];
    const float* W1  = (const float*)d_in[2];
    const float* a1s = (const float*)d_in[3];
    const float* a1d = (const float*)d_in[4];
    const float* b1  = (const float*)d_in[5];
    const float* W2  = (const float*)d_in[6];
    const float* a2s = (const float*)d_in[7];
    const float* a2d = (const float*)d_in[8];
    const float* b2  = (const float*)d_in[9];
    float*       out = (float*)d_out;

    const int Nn   = in_sizes[0] / IN_DIM;  // 50000
    const int E    = in_sizes[1] / 2;       // 800000
    const int Etot = E + Nn;

    const int nG1 = (Nn + 127) / 128;             // gemm1 blocks
    const int nH  = (E + 255) / 256;              // histo blocks
    const int nS1 = (Nn * HEADS1 + 255) / 256;    // scores1 blocks
    const int nSc = (Etot + 255) / 256;           // scatter blocks

    init_kernel<<<(Nn + 255) / 256, 256>>>((const int*)ei, Nn);
    k1_gemm1_histo<<<nG1 + nH, 256>>>(x, W1, ei, Nn, E, nG1);
    scan_kernel<<<1, 1024>>>(Nn);
    k2_scores1_scatter<<<nS1 + nSc, 256>>>(a1s, a1d, ei, Nn, E, nS1);
    agg1_kernel<<<(Nn + 7) / 8, 256>>>(b1, Nn);

    gemm2_kernel<<<(Nn + 127) / 128, 256>>>(W2, Nn);
    scores2_kernel<<<(Nn + 7) / 8, 256>>>(a2s, a2d, Nn);
    agg2_kernel<<<(Nn + 7) / 8, 256>>>(b2, out, Nn);
}